// round 2
// baseline (speedup 1.0000x reference)
#include <cuda_runtime.h>
#include <math.h>

#define BATCH   512          // fixed by the problem's setup_inputs
#define CHUNK_RES 16         // residues per chunk (48 points)
#define MAXK    256          // supports up to 4096 residues

// Scratch: chunk products and chunk-prefix frames, layout [k][j][b] (12 floats per frame)
__device__ float g_chunk [MAXK * 12 * BATCH];
__device__ float g_prefix[MAXK * 12 * BATCH];

struct Geom { float rc[3]; float rs[3]; };

struct Frame {
    float r00, r01, r02, r10, r11, r12, r20, r21, r22;
    float tx, ty, tz;
};

__device__ __forceinline__ void frame_identity(Frame& f) {
    f.r00 = 1.f; f.r01 = 0.f; f.r02 = 0.f;
    f.r10 = 0.f; f.r11 = 1.f; f.r12 = 0.f;
    f.r20 = 0.f; f.r21 = 0.f; f.r22 = 1.f;
    f.tx = 0.f; f.ty = 0.f; f.tz = 0.f;
}

// F = F ∘ G(p): G columns [u, n×u, n], u = normalize(p), n = normalize((0,-uz,uy)), t_G = p.
// After this, (f.tx, f.ty, f.tz) is the emitted global coordinate for this step.
__device__ __forceinline__ void extend(Frame& f, float px, float py, float pz) {
    float inv = rsqrtf(fmaf(px, px, fmaf(py, py, pz * pz)) + 1e-12f);
    float ux = px * inv, uy = py * inv, uz = pz * inv;
    float invn = rsqrtf(fmaf(uy, uy, uz * uz) + 1e-12f);
    float ny = -uz * invn, nz = uy * invn;           // nx = 0
    float vx = ny * uz - nz * uy;                    // v = n × u
    float vy = nz * ux;
    float vz = -ny * ux;
    float tx = f.r00 * px + f.r01 * py + f.r02 * pz + f.tx;
    float ty = f.r10 * px + f.r11 * py + f.r12 * pz + f.ty;
    float tz = f.r20 * px + f.r21 * py + f.r22 * pz + f.tz;
    float a00 = f.r00 * ux + f.r01 * uy + f.r02 * uz;
    float a01 = f.r00 * vx + f.r01 * vy + f.r02 * vz;
    float a02 =              f.r01 * ny + f.r02 * nz;
    float a10 = f.r10 * ux + f.r11 * uy + f.r12 * uz;
    float a11 = f.r10 * vx + f.r11 * vy + f.r12 * vz;
    float a12 =              f.r11 * ny + f.r12 * nz;
    float a20 = f.r20 * ux + f.r21 * uy + f.r22 * uz;
    float a21 = f.r20 * vx + f.r21 * vy + f.r22 * vz;
    float a22 =              f.r21 * ny + f.r22 * nz;
    f.r00 = a00; f.r01 = a01; f.r02 = a02;
    f.r10 = a10; f.r11 = a11; f.r12 = a12;
    f.r20 = a20; f.r21 = a21; f.r22 = a22;
    f.tx = tx; f.ty = ty; f.tz = tz;
}

// f = f ∘ g (rigid-transform composition)
__device__ __forceinline__ void compose(Frame& f, const Frame& g) {
    float tx = f.r00 * g.tx + f.r01 * g.ty + f.r02 * g.tz + f.tx;
    float ty = f.r10 * g.tx + f.r11 * g.ty + f.r12 * g.tz + f.ty;
    float tz = f.r20 * g.tx + f.r21 * g.ty + f.r22 * g.tz + f.tz;
    float a00 = f.r00 * g.r00 + f.r01 * g.r10 + f.r02 * g.r20;
    float a01 = f.r00 * g.r01 + f.r01 * g.r11 + f.r02 * g.r21;
    float a02 = f.r00 * g.r02 + f.r01 * g.r12 + f.r02 * g.r22;
    float a10 = f.r10 * g.r00 + f.r11 * g.r10 + f.r12 * g.r20;
    float a11 = f.r10 * g.r01 + f.r11 * g.r11 + f.r12 * g.r21;
    float a12 = f.r10 * g.r02 + f.r11 * g.r12 + f.r12 * g.r22;
    float a20 = f.r20 * g.r00 + f.r21 * g.r10 + f.r22 * g.r20;
    float a21 = f.r20 * g.r01 + f.r21 * g.r11 + f.r22 * g.r21;
    float a22 = f.r20 * g.r02 + f.r21 * g.r12 + f.r22 * g.r22;
    f.r00 = a00; f.r01 = a01; f.r02 = a02;
    f.r10 = a10; f.r11 = a11; f.r12 = a12;
    f.r20 = a20; f.r21 = a21; f.r22 = a22;
    f.tx = tx; f.ty = ty; f.tz = tz;
}

__device__ __forceinline__ void store_frame(float* base, const Frame& f) {
    base[0 * BATCH] = f.r00; base[1 * BATCH]  = f.r01; base[2 * BATCH]  = f.r02;
    base[3 * BATCH] = f.r10; base[4 * BATCH]  = f.r11; base[5 * BATCH]  = f.r12;
    base[6 * BATCH] = f.r20; base[7 * BATCH]  = f.r21; base[8 * BATCH]  = f.r22;
    base[9 * BATCH] = f.tx;  base[10 * BATCH] = f.ty;  base[11 * BATCH] = f.tz;
}

__device__ __forceinline__ void load_frame(const float* base, Frame& f) {
    f.r00 = base[0 * BATCH]; f.r01 = base[1 * BATCH];  f.r02 = base[2 * BATCH];
    f.r10 = base[3 * BATCH]; f.r11 = base[4 * BATCH];  f.r12 = base[5 * BATCH];
    f.r20 = base[6 * BATCH]; f.r21 = base[7 * BATCH];  f.r22 = base[8 * BATCH];
    f.tx  = base[9 * BATCH]; f.ty  = base[10 * BATCH]; f.tz  = base[11 * BATCH];
}

// Per-chain geometry selection: point m = 3l+q of chain b uses flat-dihedral
// element D[l*1536 + q*512 + b] and geometry index g = (q*512 + b) % 3.
__device__ __forceinline__ void chain_geom(const Geom& gm, int b,
                                           float& rcA, float& rsA,
                                           float& rcB, float& rsB,
                                           float& rcC, float& rsC) {
    int g0 = b % 3;
    int g1 = (b + 2) % 3;   // (b + 512) % 3
    int g2 = (b + 1) % 3;   // (b + 1024) % 3
    rcA = (g0 == 0) ? gm.rc[0] : (g0 == 1 ? gm.rc[1] : gm.rc[2]);
    rsA = (g0 == 0) ? gm.rs[0] : (g0 == 1 ? gm.rs[1] : gm.rs[2]);
    rcB = (g1 == 0) ? gm.rc[0] : (g1 == 1 ? gm.rc[1] : gm.rc[2]);
    rsB = (g1 == 0) ? gm.rs[0] : (g1 == 1 ? gm.rs[1] : gm.rs[2]);
    rcC = (g2 == 0) ? gm.rc[0] : (g2 == 1 ? gm.rc[1] : gm.rc[2]);
    rsC = (g2 == 0) ? gm.rs[0] : (g2 == 1 ? gm.rs[1] : gm.rs[2]);
}

// Kernel A: per-(chain, chunk) product of the chunk's step transforms.
__global__ __launch_bounds__(256)
void kA(const float* __restrict__ dih, Geom gm, int K, int LRES) {
    int idx = blockIdx.x * blockDim.x + threadIdx.x;
    if (idx >= BATCH * K) return;
    int b = idx & (BATCH - 1);
    int k = idx >> 9;   // / BATCH

    float rcA, rsA, rcB, rsB, rcC, rsC;
    chain_geom(gm, b, rcA, rsA, rcB, rsB, rcC, rsC);

    Frame f; frame_identity(f);
    int l0 = k * CHUNK_RES;
    int l1 = min(LRES, l0 + CHUNK_RES);
    for (int l = l0; l < l1; l++) {
        const float* dp = dih + (size_t)l * (3 * BATCH) + b;
        float d0 = dp[0], d1 = dp[BATCH], d2 = dp[2 * BATCH];
        float s, c;
        __sincosf(d0, &s, &c); extend(f, rcA, c * rsA, s * rsA);
        __sincosf(d1, &s, &c); extend(f, rcB, c * rsB, s * rsB);
        __sincosf(d2, &s, &c); extend(f, rcC, c * rsC, s * rsC);
    }
    store_frame(g_chunk + (size_t)k * 12 * BATCH + b, f);
}

// Kernel B: serial exclusive scan over chunk products, one thread per chain.
__global__ __launch_bounds__(128)
void kB(int K) {
    int b = blockIdx.x * blockDim.x + threadIdx.x;
    if (b >= BATCH) return;
    Frame f; frame_identity(f);
    for (int k = 0; k < K; k++) {
        store_frame(g_prefix + (size_t)k * 12 * BATCH + b, f);  // frame BEFORE chunk k
        Frame g;
        load_frame(g_chunk + (size_t)k * 12 * BATCH + b, g);
        compose(f, g);
    }
}

// Kernel C: replay each chunk from its prefix frame, emitting coordinates.
__global__ __launch_bounds__(256)
void kC(const float* __restrict__ dih, Geom gm, float* __restrict__ out, int K, int LRES) {
    int idx = blockIdx.x * blockDim.x + threadIdx.x;
    if (idx >= BATCH * K) return;
    int b = idx & (BATCH - 1);
    int k = idx >> 9;

    float rcA, rsA, rcB, rsB, rcC, rsC;
    chain_geom(gm, b, rcA, rsA, rcB, rsB, rcC, rsC);

    Frame f;
    load_frame(g_prefix + (size_t)k * 12 * BATCH + b, f);

    int l0 = k * CHUNK_RES;
    int l1 = min(LRES, l0 + CHUNK_RES);
    for (int l = l0; l < l1; l++) {
        const float* dp = dih + (size_t)l * (3 * BATCH) + b;
        float d0 = dp[0], d1 = dp[BATCH], d2 = dp[2 * BATCH];
        float s, c;
        float* o = out + ((size_t)(3 * l) * BATCH + b) * 3;

        __sincosf(d0, &s, &c); extend(f, rcA, c * rsA, s * rsA);
        o[0] = f.tx; o[1] = f.ty; o[2] = f.tz;
        o += (size_t)BATCH * 3;
        __sincosf(d1, &s, &c); extend(f, rcB, c * rsB, s * rsB);
        o[0] = f.tx; o[1] = f.ty; o[2] = f.tz;
        o += (size_t)BATCH * 3;
        __sincosf(d2, &s, &c); extend(f, rcC, c * rsC, s * rsC);
        o[0] = f.tx; o[1] = f.ty; o[2] = f.tz;
    }
}

extern "C" void kernel_launch(void* const* d_in, const int* in_sizes, int n_in,
                              void* d_out, int out_size) {
    const float* dih = (const float*)d_in[0];
    float* out = (float*)d_out;

    int Npts = in_sizes[0] / BATCH;               // total chain points = 3 * residues
    int LRES = Npts / 3;                          // residues (scan length / 3)
    int K = (LRES + CHUNK_RES - 1) / CHUNK_RES;
    if (K > MAXK) K = MAXK;                       // safety (not hit for this problem)

    // Geometry constants computed in double to match the numpy reference.
    const double PI = 3.14159265358979323846;
    const float BL[3] = {145.801f, 152.326f, 132.868f};
    const float BA[3] = {2.124f, 1.941f, 2.028f};
    Geom gm;
    for (int d = 0; d < 3; d++) {
        double a = PI - (double)BA[d];
        gm.rc[d] = (float)((double)BL[d] * cos(a));
        gm.rs[d] = (float)((double)BL[d] * sin(a));
    }

    int threadsA = BATCH * K;
    kA<<<(threadsA + 255) / 256, 256>>>(dih, gm, K, LRES);
    kB<<<(BATCH + 127) / 128, 128>>>(K);
    kC<<<(threadsA + 255) / 256, 256>>>(dih, gm, out, K, LRES);
}

// round 3
// speedup vs baseline: 1.4482x; 1.4482x over previous
#include <cuda_runtime.h>
#include <math.h>

#define BATCH      512       // fixed by the problem's setup_inputs
#define CHUNK_RES  8         // residues per chunk (24 points)
#define MAXK       512       // chunks per chain supported
#define SUPW       8         // chunks per superchunk
#define MAXSUP     (MAXK / SUPW)

// Scratch frames, layout [k][j][b] (12 floats per frame)
__device__ float g_chunk  [MAXK   * 12 * BATCH];
__device__ float g_prefix [MAXK   * 12 * BATCH];
__device__ float g_super  [MAXSUP * 12 * BATCH];
__device__ float g_sprefix[MAXSUP * 12 * BATCH];

// Per-geometry constants: ux = rc/L, kk = rs/L, L (bond length)
struct Geom { float ux[3]; float kk[3]; float L[3]; };

struct Frame {
    float r00, r01, r02, r10, r11, r12, r20, r21, r22;
    float tx, ty, tz;
};

__device__ __forceinline__ void frame_identity(Frame& f) {
    f.r00 = 1.f; f.r01 = 0.f; f.r02 = 0.f;
    f.r10 = 0.f; f.r11 = 1.f; f.r12 = 0.f;
    f.r20 = 0.f; f.r21 = 0.f; f.r22 = 1.f;
    f.tx = 0.f; f.ty = 0.f; f.tz = 0.f;
}

// F = F ∘ G(s,c | geometry). Closed-form G (no normalization needed):
//   u = (ux, c*kk, s*kk)   (unit),  n = (0, -s, c),  v = n×u = (-kk, c*ux, s*ux)
//   t_G = L*u.  After this, (tx,ty,tz) is the emitted global coordinate.
__device__ __forceinline__ void extend(Frame& f, float s, float c,
                                       float ux, float kk, float L) {
    float ck  = c * kk, sk  = s * kk;
    float cux = c * ux, sux = s * ux;
    // col0 = R·u
    float a00 = fmaf(f.r00, ux, fmaf(f.r01, ck, f.r02 * sk));
    float a10 = fmaf(f.r10, ux, fmaf(f.r11, ck, f.r12 * sk));
    float a20 = fmaf(f.r20, ux, fmaf(f.r21, ck, f.r22 * sk));
    // col1 = R·v
    float a01 = fmaf(f.r01, cux, fmaf(f.r02, sux, -f.r00 * kk));
    float a11 = fmaf(f.r11, cux, fmaf(f.r12, sux, -f.r10 * kk));
    float a21 = fmaf(f.r21, cux, fmaf(f.r22, sux, -f.r20 * kk));
    // col2 = R·n
    float a02 = fmaf(f.r02, c, -f.r01 * s);
    float a12 = fmaf(f.r12, c, -f.r11 * s);
    float a22 = fmaf(f.r22, c, -f.r21 * s);
    // t' = L*col0 + t
    f.tx = fmaf(L, a00, f.tx);
    f.ty = fmaf(L, a10, f.ty);
    f.tz = fmaf(L, a20, f.tz);
    f.r00 = a00; f.r01 = a01; f.r02 = a02;
    f.r10 = a10; f.r11 = a11; f.r12 = a12;
    f.r20 = a20; f.r21 = a21; f.r22 = a22;
}

// f = f ∘ g (rigid-transform composition)
__device__ __forceinline__ void compose(Frame& f, const Frame& g) {
    float tx = fmaf(f.r00, g.tx, fmaf(f.r01, g.ty, fmaf(f.r02, g.tz, f.tx)));
    float ty = fmaf(f.r10, g.tx, fmaf(f.r11, g.ty, fmaf(f.r12, g.tz, f.ty)));
    float tz = fmaf(f.r20, g.tx, fmaf(f.r21, g.ty, fmaf(f.r22, g.tz, f.tz)));
    float a00 = fmaf(f.r00, g.r00, fmaf(f.r01, g.r10, f.r02 * g.r20));
    float a01 = fmaf(f.r00, g.r01, fmaf(f.r01, g.r11, f.r02 * g.r21));
    float a02 = fmaf(f.r00, g.r02, fmaf(f.r01, g.r12, f.r02 * g.r22));
    float a10 = fmaf(f.r10, g.r00, fmaf(f.r11, g.r10, f.r12 * g.r20));
    float a11 = fmaf(f.r10, g.r01, fmaf(f.r11, g.r11, f.r12 * g.r21));
    float a12 = fmaf(f.r10, g.r02, fmaf(f.r11, g.r12, f.r12 * g.r22));
    float a20 = fmaf(f.r20, g.r00, fmaf(f.r21, g.r10, f.r22 * g.r20));
    float a21 = fmaf(f.r20, g.r01, fmaf(f.r21, g.r11, f.r22 * g.r21));
    float a22 = fmaf(f.r20, g.r02, fmaf(f.r21, g.r12, f.r22 * g.r22));
    f.r00 = a00; f.r01 = a01; f.r02 = a02;
    f.r10 = a10; f.r11 = a11; f.r12 = a12;
    f.r20 = a20; f.r21 = a21; f.r22 = a22;
    f.tx = tx; f.ty = ty; f.tz = tz;
}

__device__ __forceinline__ void store_frame(float* base, const Frame& f) {
    base[0 * BATCH] = f.r00; base[1 * BATCH]  = f.r01; base[2 * BATCH]  = f.r02;
    base[3 * BATCH] = f.r10; base[4 * BATCH]  = f.r11; base[5 * BATCH]  = f.r12;
    base[6 * BATCH] = f.r20; base[7 * BATCH]  = f.r21; base[8 * BATCH]  = f.r22;
    base[9 * BATCH] = f.tx;  base[10 * BATCH] = f.ty;  base[11 * BATCH] = f.tz;
}

__device__ __forceinline__ void load_frame(const float* base, Frame& f) {
    f.r00 = base[0 * BATCH]; f.r01 = base[1 * BATCH];  f.r02 = base[2 * BATCH];
    f.r10 = base[3 * BATCH]; f.r11 = base[4 * BATCH];  f.r12 = base[5 * BATCH];
    f.r20 = base[6 * BATCH]; f.r21 = base[7 * BATCH];  f.r22 = base[8 * BATCH];
    f.tx  = base[9 * BATCH]; f.ty  = base[10 * BATCH]; f.tz  = base[11 * BATCH];
}

// Per-chain geometry selection. Due to the reference's reshape, point m = 3l+q
// of chain b uses flat element D[l*1536 + q*512 + b], geometry (q*512 + b) % 3.
__device__ __forceinline__ int sel(int g) { return g; }
__device__ __forceinline__ void chain_geom(const Geom& gm, int b,
                                           float* uxs, float* kks, float* Ls) {
    int g0 = b % 3;
    int g1 = (b + 2) % 3;
    int g2 = (b + 1) % 3;
    uxs[0] = gm.ux[g0]; kks[0] = gm.kk[g0]; Ls[0] = gm.L[g0];
    uxs[1] = gm.ux[g1]; kks[1] = gm.kk[g1]; Ls[1] = gm.L[g1];
    uxs[2] = gm.ux[g2]; kks[2] = gm.kk[g2]; Ls[2] = gm.L[g2];
}

// Kernel A: per-(chain, chunk) product of the chunk's step transforms.
__global__ __launch_bounds__(256)
void kA(const float* __restrict__ dih, Geom gm, int K, int LRES) {
    int idx = blockIdx.x * blockDim.x + threadIdx.x;
    if (idx >= BATCH * K) return;
    int b = idx & (BATCH - 1);
    int k = idx >> 9;

    float uxs[3], kks[3], Ls[3];
    chain_geom(gm, b, uxs, kks, Ls);

    Frame f; frame_identity(f);
    int l0 = k * CHUNK_RES;
    int l1 = min(LRES, l0 + CHUNK_RES);
    for (int l = l0; l < l1; l++) {
        const float* dp = dih + (size_t)l * (3 * BATCH) + b;
        float d0 = dp[0], d1 = dp[BATCH], d2 = dp[2 * BATCH];
        float s, c;
        __sincosf(d0, &s, &c); extend(f, s, c, uxs[0], kks[0], Ls[0]);
        __sincosf(d1, &s, &c); extend(f, s, c, uxs[1], kks[1], Ls[1]);
        __sincosf(d2, &s, &c); extend(f, s, c, uxs[2], kks[2], Ls[2]);
    }
    store_frame(g_chunk + (size_t)k * 12 * BATCH + b, f);
}

// Kernel B1: compose SUPW chunk products into superchunk products.
__global__ __launch_bounds__(256)
void kB1(int K, int NSUP) {
    int idx = blockIdx.x * blockDim.x + threadIdx.x;
    if (idx >= BATCH * NSUP) return;
    int b = idx & (BATCH - 1);
    int ss = idx >> 9;
    Frame f; frame_identity(f);
    int k0 = ss * SUPW, k1 = min(K, k0 + SUPW);
    for (int k = k0; k < k1; k++) {
        Frame g; load_frame(g_chunk + (size_t)k * 12 * BATCH + b, g);
        compose(f, g);
    }
    store_frame(g_super + (size_t)ss * 12 * BATCH + b, f);
}

// Kernel B2: serial exclusive scan over superchunk products (one thread/chain).
__global__ __launch_bounds__(256)
void kB2(int NSUP) {
    int b = blockIdx.x * blockDim.x + threadIdx.x;
    if (b >= BATCH) return;
    Frame f; frame_identity(f);
    for (int ss = 0; ss < NSUP; ss++) {
        store_frame(g_sprefix + (size_t)ss * 12 * BATCH + b, f);
        Frame g; load_frame(g_super + (size_t)ss * 12 * BATCH + b, g);
        compose(f, g);
    }
}

// Kernel B3: distribute superchunk prefixes to per-chunk prefixes.
__global__ __launch_bounds__(256)
void kB3(int K, int NSUP) {
    int idx = blockIdx.x * blockDim.x + threadIdx.x;
    if (idx >= BATCH * NSUP) return;
    int b = idx & (BATCH - 1);
    int ss = idx >> 9;
    Frame f; load_frame(g_sprefix + (size_t)ss * 12 * BATCH + b, f);
    int k0 = ss * SUPW, k1 = min(K, k0 + SUPW);
    for (int k = k0; k < k1; k++) {
        store_frame(g_prefix + (size_t)k * 12 * BATCH + b, f);
        Frame g; load_frame(g_chunk + (size_t)k * 12 * BATCH + b, g);
        compose(f, g);
    }
}

// Kernel C: replay each chunk from its prefix frame, emitting coordinates.
__global__ __launch_bounds__(256)
void kC(const float* __restrict__ dih, Geom gm, float* __restrict__ out, int K, int LRES) {
    int idx = blockIdx.x * blockDim.x + threadIdx.x;
    if (idx >= BATCH * K) return;
    int b = idx & (BATCH - 1);
    int k = idx >> 9;

    float uxs[3], kks[3], Ls[3];
    chain_geom(gm, b, uxs, kks, Ls);

    Frame f;
    load_frame(g_prefix + (size_t)k * 12 * BATCH + b, f);

    int l0 = k * CHUNK_RES;
    int l1 = min(LRES, l0 + CHUNK_RES);
    for (int l = l0; l < l1; l++) {
        const float* dp = dih + (size_t)l * (3 * BATCH) + b;
        float d0 = dp[0], d1 = dp[BATCH], d2 = dp[2 * BATCH];
        float s, c;
        float* o = out + ((size_t)(3 * l) * BATCH + b) * 3;

        __sincosf(d0, &s, &c); extend(f, s, c, uxs[0], kks[0], Ls[0]);
        o[0] = f.tx; o[1] = f.ty; o[2] = f.tz;
        o += (size_t)BATCH * 3;
        __sincosf(d1, &s, &c); extend(f, s, c, uxs[1], kks[1], Ls[1]);
        o[0] = f.tx; o[1] = f.ty; o[2] = f.tz;
        o += (size_t)BATCH * 3;
        __sincosf(d2, &s, &c); extend(f, s, c, uxs[2], kks[2], Ls[2]);
        o[0] = f.tx; o[1] = f.ty; o[2] = f.tz;
    }
}

extern "C" void kernel_launch(void* const* d_in, const int* in_sizes, int n_in,
                              void* d_out, int out_size) {
    const float* dih = (const float*)d_in[0];
    float* out = (float*)d_out;

    int Npts = in_sizes[0] / BATCH;               // total chain points = 3 * residues
    int LRES = Npts / 3;
    int K = (LRES + CHUNK_RES - 1) / CHUNK_RES;
    if (K > MAXK) K = MAXK;
    int NSUP = (K + SUPW - 1) / SUPW;

    // Geometry constants in double to match the numpy reference.
    const double PI = 3.14159265358979323846;
    const float BL[3] = {145.801f, 152.326f, 132.868f};
    const float BA[3] = {2.124f, 1.941f, 2.028f};
    Geom gm;
    for (int d = 0; d < 3; d++) {
        double a  = PI - (double)BA[d];
        double rc = (double)BL[d] * cos(a);
        double rs = (double)BL[d] * sin(a);
        double L  = sqrt(rc * rc + rs * rs);
        gm.ux[d] = (float)(rc / L);
        gm.kk[d] = (float)(rs / L);
        gm.L[d]  = (float)L;
    }

    int nAC = BATCH * K;
    int nB  = BATCH * NSUP;
    kA <<<(nAC + 255) / 256, 256>>>(dih, gm, K, LRES);
    kB1<<<(nB  + 255) / 256, 256>>>(K, NSUP);
    kB2<<<(BATCH + 255) / 256, 256>>>(NSUP);
    kB3<<<(nB  + 255) / 256, 256>>>(K, NSUP);
    kC <<<(nAC + 255) / 256, 256>>>(dih, gm, out, K, LRES);
}

// round 4
// speedup vs baseline: 1.9317x; 1.3339x over previous
#include <cuda_runtime.h>
#include <math.h>

#define BATCH      512       // fixed by the problem's setup_inputs
#define CHUNK_RES  8         // residues per chunk (24 points)
#define MAXK       512       // chunks per chain supported

// Scratch frames, layout [k][j][b] (12 floats per frame)
__device__ float g_chunk  [MAXK * 12 * BATCH];
__device__ float g_sprefix[32   * 12 * BATCH];

// Per-geometry constants: ux = rc/L, kk = rs/L, L (bond length)
struct Geom { float ux[3]; float kk[3]; float L[3]; };

struct Frame {
    float r00, r01, r02, r10, r11, r12, r20, r21, r22;
    float tx, ty, tz;
};

__device__ __forceinline__ void frame_identity(Frame& f) {
    f.r00 = 1.f; f.r01 = 0.f; f.r02 = 0.f;
    f.r10 = 0.f; f.r11 = 1.f; f.r12 = 0.f;
    f.r20 = 0.f; f.r21 = 0.f; f.r22 = 1.f;
    f.tx = 0.f; f.ty = 0.f; f.tz = 0.f;
}

// F = F ∘ G(s,c | geometry). Closed-form G:
//   u = (ux, c*kk, s*kk) (unit), n = (0,-s,c), v = n×u = (-kk, c*ux, s*ux), t_G = L*u
__device__ __forceinline__ void extend(Frame& f, float s, float c,
                                       float ux, float kk, float L) {
    float ck  = c * kk, sk  = s * kk;
    float cux = c * ux, sux = s * ux;
    float a00 = fmaf(f.r00, ux, fmaf(f.r01, ck, f.r02 * sk));
    float a10 = fmaf(f.r10, ux, fmaf(f.r11, ck, f.r12 * sk));
    float a20 = fmaf(f.r20, ux, fmaf(f.r21, ck, f.r22 * sk));
    float a01 = fmaf(f.r01, cux, fmaf(f.r02, sux, -f.r00 * kk));
    float a11 = fmaf(f.r11, cux, fmaf(f.r12, sux, -f.r10 * kk));
    float a21 = fmaf(f.r21, cux, fmaf(f.r22, sux, -f.r20 * kk));
    float a02 = fmaf(f.r02, c, -f.r01 * s);
    float a12 = fmaf(f.r12, c, -f.r11 * s);
    float a22 = fmaf(f.r22, c, -f.r21 * s);
    f.tx = fmaf(L, a00, f.tx);
    f.ty = fmaf(L, a10, f.ty);
    f.tz = fmaf(L, a20, f.tz);
    f.r00 = a00; f.r01 = a01; f.r02 = a02;
    f.r10 = a10; f.r11 = a11; f.r12 = a12;
    f.r20 = a20; f.r21 = a21; f.r22 = a22;
}

// f = f ∘ g
__device__ __forceinline__ void compose(Frame& f, const Frame& g) {
    float tx = fmaf(f.r00, g.tx, fmaf(f.r01, g.ty, fmaf(f.r02, g.tz, f.tx)));
    float ty = fmaf(f.r10, g.tx, fmaf(f.r11, g.ty, fmaf(f.r12, g.tz, f.ty)));
    float tz = fmaf(f.r20, g.tx, fmaf(f.r21, g.ty, fmaf(f.r22, g.tz, f.tz)));
    float a00 = fmaf(f.r00, g.r00, fmaf(f.r01, g.r10, f.r02 * g.r20));
    float a01 = fmaf(f.r00, g.r01, fmaf(f.r01, g.r11, f.r02 * g.r21));
    float a02 = fmaf(f.r00, g.r02, fmaf(f.r01, g.r12, f.r02 * g.r22));
    float a10 = fmaf(f.r10, g.r00, fmaf(f.r11, g.r10, f.r12 * g.r20));
    float a11 = fmaf(f.r10, g.r01, fmaf(f.r11, g.r11, f.r12 * g.r21));
    float a12 = fmaf(f.r10, g.r02, fmaf(f.r11, g.r12, f.r12 * g.r22));
    float a20 = fmaf(f.r20, g.r00, fmaf(f.r21, g.r10, f.r22 * g.r20));
    float a21 = fmaf(f.r20, g.r01, fmaf(f.r21, g.r11, f.r22 * g.r21));
    float a22 = fmaf(f.r20, g.r02, fmaf(f.r21, g.r12, f.r22 * g.r22));
    f.r00 = a00; f.r01 = a01; f.r02 = a02;
    f.r10 = a10; f.r11 = a11; f.r12 = a12;
    f.r20 = a20; f.r21 = a21; f.r22 = a22;
    f.tx = tx; f.ty = ty; f.tz = tz;
}

__device__ __forceinline__ void store_frame(float* base, const Frame& f) {
    base[0 * BATCH] = f.r00; base[1 * BATCH]  = f.r01; base[2 * BATCH]  = f.r02;
    base[3 * BATCH] = f.r10; base[4 * BATCH]  = f.r11; base[5 * BATCH]  = f.r12;
    base[6 * BATCH] = f.r20; base[7 * BATCH]  = f.r21; base[8 * BATCH]  = f.r22;
    base[9 * BATCH] = f.tx;  base[10 * BATCH] = f.ty;  base[11 * BATCH] = f.tz;
}

__device__ __forceinline__ void load_frame(const float* base, Frame& f) {
    f.r00 = base[0 * BATCH]; f.r01 = base[1 * BATCH];  f.r02 = base[2 * BATCH];
    f.r10 = base[3 * BATCH]; f.r11 = base[4 * BATCH];  f.r12 = base[5 * BATCH];
    f.r20 = base[6 * BATCH]; f.r21 = base[7 * BATCH];  f.r22 = base[8 * BATCH];
    f.tx  = base[9 * BATCH]; f.ty  = base[10 * BATCH]; f.tz  = base[11 * BATCH];
}

__device__ __forceinline__ Frame shfl_up_frame(const Frame& f, int d) {
    Frame o;
    o.r00 = __shfl_up_sync(0xFFFFFFFF, f.r00, d);
    o.r01 = __shfl_up_sync(0xFFFFFFFF, f.r01, d);
    o.r02 = __shfl_up_sync(0xFFFFFFFF, f.r02, d);
    o.r10 = __shfl_up_sync(0xFFFFFFFF, f.r10, d);
    o.r11 = __shfl_up_sync(0xFFFFFFFF, f.r11, d);
    o.r12 = __shfl_up_sync(0xFFFFFFFF, f.r12, d);
    o.r20 = __shfl_up_sync(0xFFFFFFFF, f.r20, d);
    o.r21 = __shfl_up_sync(0xFFFFFFFF, f.r21, d);
    o.r22 = __shfl_up_sync(0xFFFFFFFF, f.r22, d);
    o.tx  = __shfl_up_sync(0xFFFFFFFF, f.tx,  d);
    o.ty  = __shfl_up_sync(0xFFFFFFFF, f.ty,  d);
    o.tz  = __shfl_up_sync(0xFFFFFFFF, f.tz,  d);
    return o;
}

// Per-chain geometry: point m = 3l+q of chain b uses flat element
// D[l*1536 + q*512 + b], geometry index (q*512 + b) % 3.
__device__ __forceinline__ void chain_geom(const Geom& gm, int b,
                                           float* uxs, float* kks, float* Ls) {
    int g0 = b % 3;
    int g1 = (b + 2) % 3;
    int g2 = (b + 1) % 3;
    uxs[0] = gm.ux[g0]; kks[0] = gm.kk[g0]; Ls[0] = gm.L[g0];
    uxs[1] = gm.ux[g1]; kks[1] = gm.kk[g1]; Ls[1] = gm.L[g1];
    uxs[2] = gm.ux[g2]; kks[2] = gm.kk[g2]; Ls[2] = gm.L[g2];
}

// Kernel A: per-(chain, chunk) product of the chunk's step transforms.
__global__ __launch_bounds__(256)
void kA(const float* __restrict__ dih, Geom gm, int K, int LRES) {
    int idx = blockIdx.x * blockDim.x + threadIdx.x;
    if (idx >= BATCH * K) return;
    int b = idx & (BATCH - 1);
    int k = idx >> 9;

    float uxs[3], kks[3], Ls[3];
    chain_geom(gm, b, uxs, kks, Ls);

    Frame f; frame_identity(f);
    int l0 = k * CHUNK_RES;
    int l1 = min(LRES, l0 + CHUNK_RES);
    for (int l = l0; l < l1; l++) {
        const float* dp = dih + (size_t)l * (3 * BATCH) + b;
        float d0 = dp[0], d1 = dp[BATCH], d2 = dp[2 * BATCH];
        float s, c;
        __sincosf(d0, &s, &c); extend(f, s, c, uxs[0], kks[0], Ls[0]);
        __sincosf(d1, &s, &c); extend(f, s, c, uxs[1], kks[1], Ls[1]);
        __sincosf(d2, &s, &c); extend(f, s, c, uxs[2], kks[2], Ls[2]);
    }
    store_frame(g_chunk + (size_t)k * 12 * BATCH + b, f);
}

// Scan kernel: one warp per chain. Lane ss builds its superchunk product from
// SUPW chunk products (tree), then Kogge-Stone inclusive scan over lanes,
// then writes the EXCLUSIVE superchunk prefix.
__global__ __launch_bounds__(128)
void kScan(int K, int SUPW, int NSUP) {
    int warp = (blockIdx.x * blockDim.x + threadIdx.x) >> 5;
    int lane = threadIdx.x & 31;
    if (warp >= BATCH) return;
    int b = warp;

    // Build superchunk product for lane = ss (identity if ss >= NSUP)
    Frame f; frame_identity(f);
    if (lane < NSUP) {
        int k0 = lane * SUPW;
        int k1 = min(K, k0 + SUPW);
        // pairwise tree: load two, compose, fold in
        int k = k0;
        bool first = true;
        while (k < k1) {
            Frame a; load_frame(g_chunk + (size_t)k * 12 * BATCH + b, a);
            if (k + 1 < k1) {
                Frame c2; load_frame(g_chunk + (size_t)(k + 1) * 12 * BATCH + b, c2);
                compose(a, c2);
                k += 2;
            } else {
                k += 1;
            }
            if (first) { f = a; first = false; }
            else       { compose(f, a); }
        }
    }

    // Kogge-Stone inclusive scan (composition is associative)
    #pragma unroll
    for (int d = 1; d < 32; d <<= 1) {
        Frame left = shfl_up_frame(f, d);
        Frame t = left;
        compose(t, f);
        if (lane >= d) f = t;
    }

    // Exclusive prefix = inclusive of lane-1; lane 0 = identity
    Frame ex = shfl_up_frame(f, 1);
    if (lane == 0) frame_identity(ex);

    if (lane < NSUP)
        store_frame(g_sprefix + (size_t)lane * 12 * BATCH + b, ex);
}

// Kernel C: thread (b,k) assembles its chunk prefix from the superchunk
// exclusive prefix + preceding chunk products, then replays the chunk
// emitting coordinates.
__global__ __launch_bounds__(256)
void kC(const float* __restrict__ dih, Geom gm, float* __restrict__ out,
        int K, int LRES, int SUPW) {
    int idx = blockIdx.x * blockDim.x + threadIdx.x;
    if (idx >= BATCH * K) return;
    int b = idx & (BATCH - 1);
    int k = idx >> 9;
    int ss = k / SUPW;
    int k0 = ss * SUPW;

    float uxs[3], kks[3], Ls[3];
    chain_geom(gm, b, uxs, kks, Ls);

    Frame f;
    load_frame(g_sprefix + (size_t)ss * 12 * BATCH + b, f);
    for (int kk = k0; kk < k; kk++) {           // uniform across the warp
        Frame g; load_frame(g_chunk + (size_t)kk * 12 * BATCH + b, g);
        compose(f, g);
    }

    int l0 = k * CHUNK_RES;
    int l1 = min(LRES, l0 + CHUNK_RES);
    for (int l = l0; l < l1; l++) {
        const float* dp = dih + (size_t)l * (3 * BATCH) + b;
        float d0 = dp[0], d1 = dp[BATCH], d2 = dp[2 * BATCH];
        float s, c;
        float* o = out + ((size_t)(3 * l) * BATCH + b) * 3;

        __sincosf(d0, &s, &c); extend(f, s, c, uxs[0], kks[0], Ls[0]);
        o[0] = f.tx; o[1] = f.ty; o[2] = f.tz;
        o += (size_t)BATCH * 3;
        __sincosf(d1, &s, &c); extend(f, s, c, uxs[1], kks[1], Ls[1]);
        o[0] = f.tx; o[1] = f.ty; o[2] = f.tz;
        o += (size_t)BATCH * 3;
        __sincosf(d2, &s, &c); extend(f, s, c, uxs[2], kks[2], Ls[2]);
        o[0] = f.tx; o[1] = f.ty; o[2] = f.tz;
    }
}

extern "C" void kernel_launch(void* const* d_in, const int* in_sizes, int n_in,
                              void* d_out, int out_size) {
    const float* dih = (const float*)d_in[0];
    float* out = (float*)d_out;

    int Npts = in_sizes[0] / BATCH;
    int LRES = Npts / 3;
    int K = (LRES + CHUNK_RES - 1) / CHUNK_RES;
    if (K > MAXK) K = MAXK;
    int SUPW = (K + 31) / 32;                 // chunks per superchunk (lane width 32)
    int NSUP = (K + SUPW - 1) / SUPW;         // <= 32

    const double PI = 3.14159265358979323846;
    const float BL[3] = {145.801f, 152.326f, 132.868f};
    const float BA[3] = {2.124f, 1.941f, 2.028f};
    Geom gm;
    for (int d = 0; d < 3; d++) {
        double a  = PI - (double)BA[d];
        double rc = (double)BL[d] * cos(a);
        double rs = (double)BL[d] * sin(a);
        double L  = sqrt(rc * rc + rs * rs);
        gm.ux[d] = (float)(rc / L);
        gm.kk[d] = (float)(rs / L);
        gm.L[d]  = (float)L;
    }

    int nAC = BATCH * K;
    kA   <<<(nAC + 255) / 256, 256>>>(dih, gm, K, LRES);
    kScan<<<(BATCH * 32 + 127) / 128, 128>>>(K, SUPW, NSUP);
    kC   <<<(nAC + 255) / 256, 256>>>(dih, gm, out, K, LRES, SUPW);
}